// round 5
// baseline (speedup 1.0000x reference)
#include <cuda_runtime.h>
#include <math.h>

#define NN 50000
#define NE 800000
#define NET 850000
#define F 128
#define NG 256
#define NCLS 10

// ---------------- device scratch (static, no allocation) ----------------
__device__ __align__(16) float g_h0[NN * F];
__device__ __align__(16) float g_h1[NN * F];
__device__ __align__(16) float g_hp[NN * F];
__device__ __align__(16) float g_als[NN * 4];
__device__ __align__(16) float g_ald[NN * 4];
__device__ int   g_deg[NN];
__device__ int   g_off[NN + 1];
__device__ int   g_cur[NN];
__device__ int   g_bsum[128];
__device__ int   g_csrc[NET];
__device__ float g_statsA[6 * 256];                 // 6 independent (sum,sumsq) buffers
__device__ __align__(16) unsigned g_Wfrag[F * F];   // fragment-ready tf32 W'
__device__ __align__(16) float g_bpart[16 * F];     // bias partials (summed in gemm)
__device__ __align__(16) float g_pool[NG * F];
__device__ __align__(16) float g_gbuf[NG * F];

// selectors: 0=external ptr, 1=h0, 2=h1, 3=hp, 4=pool, 5=gbuf
__device__ __forceinline__ const float* sel_ptr(int sel, const float* ext) {
    switch (sel) {
        case 1: return g_h0;
        case 2: return g_h1;
        case 3: return g_hp;
        case 4: return g_pool;
        case 5: return g_gbuf;
        default: return ext;
    }
}
__device__ __forceinline__ float* sel_ptr_w(int sel) {
    switch (sel) {
        case 1: return g_h0;
        case 2: return g_h1;
        case 3: return g_hp;
        case 4: return g_pool;
        default: return g_gbuf;
    }
}

__device__ __forceinline__ unsigned f2tf(float x) {
    unsigned u;
    asm("cvt.rna.tf32.f32 %0, %1;" : "=r"(u) : "f"(x));
    return u;
}

__device__ __forceinline__ void mma_tf32(float* c, const unsigned* a, unsigned b0, unsigned b1) {
    asm volatile(
        "mma.sync.aligned.m16n8k8.row.col.f32.tf32.tf32.f32 "
        "{%0,%1,%2,%3},{%4,%5,%6,%7},{%8,%9},{%0,%1,%2,%3};"
        : "+f"(c[0]), "+f"(c[1]), "+f"(c[2]), "+f"(c[3])
        : "r"(a[0]), "r"(a[1]), "r"(a[2]), "r"(a[3]), "r"(b0), "r"(b1));
}

// ---------------- zero / init everything ----------------
__global__ void k_zeroall() {
    int i = blockIdx.x * blockDim.x + threadIdx.x;
    if (i < NN) g_deg[i] = 1;                 // self loop
    if (i < 6 * 256) g_statsA[i] = 0.f;
    if (i < NG * F) g_pool[i] = 0.f;
}

// ---------------- CSR construction ----------------
__global__ void k_count(const int* __restrict__ ei) {
    int e = blockIdx.x * blockDim.x + threadIdx.x;
    if (e < NE) atomicAdd(&g_deg[ei[NE + e]], 1);
}

#define SCAN_B 512
#define SCAN_NB ((NN + SCAN_B - 1) / SCAN_B)   // 98

__global__ void k_scanA() {
    __shared__ int wsum[16];
    int t = threadIdx.x, b = blockIdx.x;
    int i = b * SCAN_B + t;
    int v = (i < NN) ? g_deg[i] : 0;
    int lane = t & 31, w = t >> 5;
    int x = v;
#pragma unroll
    for (int o = 1; o < 32; o <<= 1) {
        int tv = __shfl_up_sync(0xffffffffu, x, o);
        if (lane >= o) x += tv;
    }
    if (lane == 31) wsum[w] = x;
    __syncthreads();
    if (w == 0) {
        int s = (lane < 16) ? wsum[lane] : 0;
#pragma unroll
        for (int o = 1; o < 16; o <<= 1) {
            int tv = __shfl_up_sync(0xffffffffu, s, o);
            if (lane >= o) s += tv;
        }
        if (lane < 16) wsum[lane] = s;
    }
    __syncthreads();
    int incl = x + ((w > 0) ? wsum[w - 1] : 0);
    if (i < NN) g_off[i] = incl - v;   // block-local exclusive
    if (t == SCAN_B - 1) g_bsum[b] = incl;
}

__global__ void k_scanB() {
    __shared__ int sh[128];
    int t = threadIdx.x;  // 128
    int v = (t < SCAN_NB) ? g_bsum[t] : 0;
    sh[t] = v;
    __syncthreads();
#pragma unroll
    for (int o = 1; o < 128; o <<= 1) {
        int p = (t >= o) ? sh[t - o] : 0;
        __syncthreads();
        sh[t] += p;
        __syncthreads();
    }
    if (t < SCAN_NB) g_bsum[t] = sh[t] - v;  // exclusive
    if (t == 127) g_off[NN] = sh[127];
}

__global__ void k_scanC() {
    int i = blockIdx.x * blockDim.x + threadIdx.x;
    if (i < NN) {
        int val = g_off[i] + g_bsum[i >> 9];
        g_off[i] = val;
        g_cur[i] = val;
    }
}

__global__ void k_fill(const int* __restrict__ ei) {
    int t = blockIdx.x * blockDim.x + threadIdx.x;
    if (t < NE) {
        int d = ei[NE + t];
        int p = atomicAdd(&g_cur[d], 1);
        g_csrc[p] = ei[t];
    } else if (t < NE + NN) {
        int i = t - NE;
        int p = atomicAdd(&g_cur[i], 1);
        g_csrc[p] = i;  // self loop
    }
}

// ---------------- BN statistics (only for x and pool) ----------------
__global__ void k_colstats(const float* __restrict__ ext, int sel, int M, int ssel) {
    const float* X = sel_ptr(sel, ext);
    int c = threadIdx.x;  // 128 threads
    int r0 = blockIdx.x * 64;
    int nr = M - r0;
    if (nr > 64) nr = 64;
    float s = 0.f, q = 0.f;
    for (int j = 0; j < nr; j++) {
        float v = X[(size_t)(r0 + j) * F + c];
        s += v;
        q += v * v;
    }
    atomicAdd(&g_statsA[ssel * 256 + c], s);
    atomicAdd(&g_statsA[ssel * 256 + F + c], q);
}

// ---------------- parallel BN fold + tf32 fragment pack ----------------
// 32 blocks x 128 threads.
// blocks 0..15 : pack g_Wfrag slice for ks = b (k rows 8b..8b+7)
// blocks 16..31: bias partials g_bpart[b-16][:] = sum_{c in 8-range} shf[c]*W[c,:]
__global__ void k_fold(const float* __restrict__ W, const float* __restrict__ gamma,
                       const float* __restrict__ beta, float invM, int ssel) {
    __shared__ float sc[F], shf[F];
    __shared__ float Ws[8 * F];
    int tid = threadIdx.x;  // 128
    int b = blockIdx.x;
    const float* st = g_statsA + ssel * 256;
    {
        float mean = st[tid] * invM;
        float var = st[F + tid] * invM - mean * mean;
        float s = rsqrtf(var + 1e-5f) * gamma[tid];
        sc[tid] = s;
        shf[tid] = beta[tid] - mean * s;
    }
    __syncthreads();
    if (b < 16) {
        // load 8 k-rows of W, scale by sc[k], pack fragments
        int ks = b;
#pragma unroll
        for (int t = tid; t < 8 * F; t += 128) {
            int row = t >> 7, col = t & 127;
            Ws[t] = sc[ks * 8 + row] * W[(size_t)(ks * 8 + row) * F + col];
        }
        __syncthreads();
#pragma unroll
        for (int t = tid; t < 1024; t += 128) {
            int r = t & 1;
            int lane = (t >> 1) & 31;
            int nt = t >> 6;
            int tg = lane & 3, gg = lane >> 2;
            int kl = tg + 4 * r;
            int n = nt * 8 + gg;
            g_Wfrag[b * 1024 + t] = f2tf(Ws[kl * F + n]);
        }
    } else {
        int cr = (b - 16) * 8;
        float acc = 0.f;
#pragma unroll
        for (int j = 0; j < 8; j++)
            acc += shf[cr + j] * W[(size_t)(cr + j) * F + tid];
        g_bpart[(b - 16) * F + tid] = acc;
    }
}

// ---------------- tf32 tensor-core GEMM + fused alpha / fused colstats ----------------
#define GEMM_SMEM ((128 * 132 + F * F + 3 * F) * 4)

__global__ __launch_bounds__(256, 1) void k_gemm(const float* __restrict__ ext_in, int sel_in,
                                                 int sel_out, int M, int relu, int do_alpha,
                                                 const float* __restrict__ asrc,
                                                 const float* __restrict__ adst,
                                                 const float* __restrict__ extrab,
                                                 int stats_sel) {
    extern __shared__ float sm[];
    float* As = sm;                                  // 128*132 (tf32 bits)
    unsigned* Bf = (unsigned*)(sm + 128 * 132);      // 16384
    float* bsh = (float*)(Bf + F * F);               // 128
    float* sas = bsh + F;
    float* sad = sas + F;
    __shared__ float sstat[256];
    const float* A = sel_ptr(sel_in, ext_in);
    float* C = sel_ptr_w(sel_out);
    int tid = threadIdx.x;
    int row0 = blockIdx.x * 128;

    for (int t = tid; t < 128 * 32; t += 256) {
        int r = t >> 5, c4 = t & 31;
        int gr = row0 + r;
        float4 v = make_float4(0.f, 0.f, 0.f, 0.f);
        if (gr < M) v = *(const float4*)(A + (size_t)gr * F + c4 * 4);
        int base = r * 132 + c4 * 4;
        As[base + 0] = __uint_as_float(f2tf(v.x));
        As[base + 1] = __uint_as_float(f2tf(v.y));
        As[base + 2] = __uint_as_float(f2tf(v.z));
        As[base + 3] = __uint_as_float(f2tf(v.w));
    }
    for (int t = tid; t < F * F / 4; t += 256)
        ((uint4*)Bf)[t] = ((const uint4*)g_Wfrag)[t];
    if (tid < 128) {
        float bb = extrab ? extrab[tid] : 0.f;
#pragma unroll
        for (int j = 0; j < 16; j++) bb += g_bpart[j * F + tid];
        bsh[tid] = bb;
        if (do_alpha) {
            sas[tid] = asrc[tid];
            sad[tid] = adst[tid];
        }
    }
    sstat[tid] = 0.f;
    __syncthreads();

    int wid = tid >> 5, lane = tid & 31;
    int wm = wid >> 1, wn = wid & 1;
    int g = lane >> 2, tig = lane & 3;
    float acc[2][8][4];
#pragma unroll
    for (int mt = 0; mt < 2; mt++)
#pragma unroll
        for (int tn = 0; tn < 8; tn++)
#pragma unroll
            for (int j = 0; j < 4; j++) acc[mt][tn][j] = 0.f;

    const uint2* Bf2 = (const uint2*)Bf;
#pragma unroll
    for (int ks = 0; ks < 16; ks++) {
        unsigned a[2][4];
#pragma unroll
        for (int mt = 0; mt < 2; mt++) {
            const float* p = As + (wm * 32 + mt * 16 + g) * 132 + ks * 8 + tig;
            a[mt][0] = __float_as_uint(p[0]);
            a[mt][1] = __float_as_uint(p[8 * 132]);
            a[mt][2] = __float_as_uint(p[4]);
            a[mt][3] = __float_as_uint(p[8 * 132 + 4]);
        }
#pragma unroll
        for (int tn = 0; tn < 8; tn++) {
            int nt = wn * 8 + tn;
            uint2 b = Bf2[(ks * 16 + nt) * 32 + lane];
            mma_tf32(acc[0][tn], a[0], b.x, b.y);
            mma_tf32(acc[1][tn], a[1], b.x, b.y);
        }
    }

    float ps[2][2][2], pd[2][2][2];
#pragma unroll
    for (int mt = 0; mt < 2; mt++)
#pragma unroll
        for (int m01 = 0; m01 < 2; m01++)
#pragma unroll
            for (int hl = 0; hl < 2; hl++) {
                ps[mt][m01][hl] = 0.f;
                pd[mt][m01][hl] = 0.f;
            }
    float cs0[8], cs1[8], cq0[8], cq1[8];
#pragma unroll
    for (int tn = 0; tn < 8; tn++) { cs0[tn] = cs1[tn] = cq0[tn] = cq1[tn] = 0.f; }

#pragma unroll
    for (int mt = 0; mt < 2; mt++) {
        int rA = row0 + wm * 32 + mt * 16 + g;
#pragma unroll
        for (int tn = 0; tn < 8; tn++) {
            int c0 = wn * 64 + tn * 8 + 2 * tig;
            float b0 = bsh[c0], b1 = bsh[c0 + 1];
            float v0 = acc[mt][tn][0] + b0;
            float v1 = acc[mt][tn][1] + b1;
            float v2 = acc[mt][tn][2] + b0;
            float v3 = acc[mt][tn][3] + b1;
            if (relu) {
                v0 = fmaxf(v0, 0.f); v1 = fmaxf(v1, 0.f);
                v2 = fmaxf(v2, 0.f); v3 = fmaxf(v3, 0.f);
            }
            if (rA < M) *(float2*)(C + (size_t)rA * F + c0) = make_float2(v0, v1);
            if (rA + 8 < M) *(float2*)(C + (size_t)(rA + 8) * F + c0) = make_float2(v2, v3);
            if (do_alpha) {
                int hl = tn >> 2;
                float s0 = sas[c0], s1 = sas[c0 + 1];
                float d0 = sad[c0], d1 = sad[c0 + 1];
                ps[mt][0][hl] += v0 * s0 + v1 * s1;
                pd[mt][0][hl] += v0 * d0 + v1 * d1;
                ps[mt][1][hl] += v2 * s0 + v3 * s1;
                pd[mt][1][hl] += v2 * d0 + v3 * d1;
            }
            if (stats_sel >= 0) {
                if (rA < M) {
                    cs0[tn] += v0; cs1[tn] += v1;
                    cq0[tn] += v0 * v0; cq1[tn] += v1 * v1;
                }
                if (rA + 8 < M) {
                    cs0[tn] += v2; cs1[tn] += v3;
                    cq0[tn] += v2 * v2; cq1[tn] += v3 * v3;
                }
            }
        }
    }

    if (do_alpha) {
#pragma unroll
        for (int mt = 0; mt < 2; mt++)
#pragma unroll
            for (int m01 = 0; m01 < 2; m01++)
#pragma unroll
                for (int hl = 0; hl < 2; hl++) {
                    float v = ps[mt][m01][hl];
                    v += __shfl_xor_sync(0xffffffffu, v, 1);
                    v += __shfl_xor_sync(0xffffffffu, v, 2);
                    ps[mt][m01][hl] = v;
                    float w = pd[mt][m01][hl];
                    w += __shfl_xor_sync(0xffffffffu, w, 1);
                    w += __shfl_xor_sync(0xffffffffu, w, 2);
                    pd[mt][m01][hl] = w;
                }
        if (tig == 0) {
#pragma unroll
            for (int mt = 0; mt < 2; mt++)
#pragma unroll
                for (int m01 = 0; m01 < 2; m01++) {
                    int row = row0 + wm * 32 + mt * 16 + m01 * 8 + g;
                    if (row < M) {
#pragma unroll
                        for (int hl = 0; hl < 2; hl++) {
                            int head = wn * 2 + hl;
                            g_als[row * 4 + head] = ps[mt][m01][hl];
                            g_ald[row * 4 + head] = pd[mt][m01][hl];
                        }
                    }
                }
        }
    }

    if (stats_sel >= 0) {
#pragma unroll
        for (int tn = 0; tn < 8; tn++) {
#pragma unroll
            for (int o = 4; o < 32; o <<= 1) {
                cs0[tn] += __shfl_xor_sync(0xffffffffu, cs0[tn], o);
                cs1[tn] += __shfl_xor_sync(0xffffffffu, cs1[tn], o);
                cq0[tn] += __shfl_xor_sync(0xffffffffu, cq0[tn], o);
                cq1[tn] += __shfl_xor_sync(0xffffffffu, cq1[tn], o);
            }
            if (lane < 4) {
                int c0 = wn * 64 + tn * 8 + 2 * lane;
                atomicAdd(&sstat[c0], cs0[tn]);
                atomicAdd(&sstat[c0 + 1], cs1[tn]);
                atomicAdd(&sstat[128 + c0], cq0[tn]);
                atomicAdd(&sstat[128 + c0 + 1], cq1[tn]);
            }
        }
        __syncthreads();
        atomicAdd(&g_statsA[stats_sel * 256 + tid], sstat[tid]);
    }
}

// ---------------- aggregation: warp per dst node + fused colstats ----------------
__global__ __launch_bounds__(256) void k_agg(const float* __restrict__ gbias, int sel_out,
                                             int stats_sel) {
    __shared__ float sstat[256];
    float* out = sel_ptr_w(sel_out);
    int tid = threadIdx.x;
    int gw = (blockIdx.x * blockDim.x + tid) >> 5;
    int lane = tid & 31;
    if (stats_sel >= 0) sstat[tid] = 0.f;
    int h = lane >> 3;
    float4 o = make_float4(0.f, 0.f, 0.f, 0.f);
    if (gw < NN) {
        int s0 = g_off[gw], s1 = g_off[gw + 1];
        float aldh = g_ald[gw * 4 + h];
        float a0 = 0.f, a1 = 0.f, a2 = 0.f, a3 = 0.f, ss = 0.f;
        const float4* hp4 = (const float4*)g_hp;
        for (int e = s0; e < s1; ++e) {
            int s = g_csrc[e];
            float l = g_als[s * 4 + h] + aldh;
            l = l > 0.f ? l : 0.2f * l;
            float wgt = __expf(l);
            ss += wgt;
            float4 v = hp4[(size_t)s * 32 + lane];
            a0 += wgt * v.x;
            a1 += wgt * v.y;
            a2 += wgt * v.z;
            a3 += wgt * v.w;
        }
        float inv = 1.0f / (ss + 1e-16f);
        float4 gb = ((const float4*)gbias)[lane];
        o.x = fmaxf(a0 * inv + gb.x, 0.f);
        o.y = fmaxf(a1 * inv + gb.y, 0.f);
        o.z = fmaxf(a2 * inv + gb.z, 0.f);
        o.w = fmaxf(a3 * inv + gb.w, 0.f);
        ((float4*)out)[(size_t)gw * 32 + lane] = o;
    }
    if (stats_sel >= 0) {
        __syncthreads();
        if (gw < NN) {
            int c = 4 * lane;
            atomicAdd(&sstat[c + 0], o.x);
            atomicAdd(&sstat[c + 1], o.y);
            atomicAdd(&sstat[c + 2], o.z);
            atomicAdd(&sstat[c + 3], o.w);
            atomicAdd(&sstat[128 + c + 0], o.x * o.x);
            atomicAdd(&sstat[128 + c + 1], o.y * o.y);
            atomicAdd(&sstat[128 + c + 2], o.z * o.z);
            atomicAdd(&sstat[128 + c + 3], o.w * o.w);
        }
        __syncthreads();
        atomicAdd(&g_statsA[stats_sel * 256 + tid], sstat[tid]);
    }
}

// ---------------- pooling (batch sorted) ----------------
__global__ void k_pool(const int* __restrict__ batch, int sel_in) {
    const float* X = sel_ptr(sel_in, nullptr);
    __shared__ int bsh[64];
    int r0 = blockIdx.x * 64;
    int tid = threadIdx.x;  // 128
    int nr = NN - r0;
    if (nr > 64) nr = 64;
    if (tid < nr) bsh[tid] = batch[r0 + tid];
    __syncthreads();
    float acc = 0.f;
    int cur = bsh[0];
    for (int j = 0; j < nr; j++) {
        int b = bsh[j];
        if (b != cur) {
            atomicAdd(&g_pool[(size_t)cur * F + tid], acc);
            acc = 0.f;
            cur = b;
        }
        acc += X[(size_t)(r0 + j) * F + tid];
    }
    atomicAdd(&g_pool[(size_t)cur * F + tid], acc);
}

// ---------------- final head: BN + cls GEMM + log_softmax ----------------
__global__ void k_head(const float* __restrict__ bnh_g, const float* __restrict__ bnh_b,
                       const float* __restrict__ cls_w, const float* __restrict__ cls_b,
                       float* __restrict__ out, int ssel) {
    __shared__ float sc[F], shf[F];
    int r = blockIdx.x;       // 256 rows
    int lane = threadIdx.x;   // 32 threads
    const float invM = 1.0f / (float)NG;
    const float* st = g_statsA + ssel * 256;
    for (int c = lane; c < F; c += 32) {
        float mean = st[c] * invM;
        float var = st[F + c] * invM - mean * mean;
        float rs = rsqrtf(var + 1e-5f);
        float s = rs * bnh_g[c];
        sc[c] = s;
        shf[c] = bnh_b[c] - mean * s;
    }
    __syncwarp();
    float logit = 0.f;
    if (lane < NCLS) {
        logit = cls_b[lane];
        for (int c = 0; c < F; c++)
            logit += (g_gbuf[(size_t)r * F + c] * sc[c] + shf[c]) * cls_w[c * NCLS + lane];
    }
    float v = (lane < NCLS) ? logit : -3.0e38f;
    float m = v;
#pragma unroll
    for (int o = 16; o; o >>= 1) m = fmaxf(m, __shfl_xor_sync(0xffffffffu, m, o));
    float e = (lane < NCLS) ? __expf(v - m) : 0.f;
    float s = e;
#pragma unroll
    for (int o = 16; o; o >>= 1) s += __shfl_xor_sync(0xffffffffu, s, o);
    if (lane < NCLS) out[r * NCLS + lane] = v - m - logf(s);
}

// ---------------- host ----------------
extern "C" void kernel_launch(void* const* d_in, const int* in_sizes, int n_in,
                              void* d_out, int out_size) {
    const float* x       = (const float*)d_in[0];
    const int*   ei      = (const int*)d_in[1];
    const int*   batch   = (const int*)d_in[2];
    const float* w_feat  = (const float*)d_in[3];
    const float* bnf_g   = (const float*)d_in[4];
    const float* bnf_b   = (const float*)d_in[5];
    const float* bnc_g   = (const float*)d_in[6];
    const float* bnc_b   = (const float*)d_in[7];
    const float* gat_w   = (const float*)d_in[8];
    const float* gat_as  = (const float*)d_in[9];
    const float* gat_ad  = (const float*)d_in[10];
    const float* gat_b   = (const float*)d_in[11];
    const float* bnfc_g  = (const float*)d_in[12];
    const float* bnfc_b  = (const float*)d_in[13];
    const float* lin_w   = (const float*)d_in[14];
    const float* lin_b   = (const float*)d_in[15];
    const float* bnh_g   = (const float*)d_in[16];
    const float* bnh_b   = (const float*)d_in[17];
    const float* cls_w   = (const float*)d_in[18];
    const float* cls_b   = (const float*)d_in[19];
    float* out = (float*)d_out;

    cudaFuncSetAttribute(k_gemm, cudaFuncAttributeMaxDynamicSharedMemorySize, GEMM_SMEM);

    // stats buffers: 0=x, 1=h0, 2=agg0, 3=agg1, 4=pool, 5=gbuf
    k_zeroall<<<(NN + 255) / 256, 256>>>();
    k_count<<<(NE + 255) / 256, 256>>>(ei);
    k_colstats<<<(NN + 63) / 64, 128>>>(x, 0, NN, 0);
    k_fold<<<32, 128>>>(w_feat, bnf_g, bnf_b, 1.0f / (float)NN, 0);
    k_scanA<<<SCAN_NB, SCAN_B>>>();
    k_gemm<<<(NN + 127) / 128, 256, GEMM_SMEM>>>(x, 0, 1, NN, 1, 0, nullptr, nullptr,
                                                 nullptr, 1);
    k_scanB<<<1, 128>>>();
    k_scanC<<<(NN + 255) / 256, 256>>>();
    k_fill<<<(NE + NN + 255) / 256, 256>>>(ei);

    // ---- 3 GAT convs ----
    int sel_in = 1, sel_out = 2;
    for (int i = 0; i < 3; i++) {
        k_fold<<<32, 128>>>(gat_w + (size_t)i * F * F, bnc_g + i * F, bnc_b + i * F,
                            1.0f / (float)NN, 1 + i);
        k_gemm<<<(NN + 127) / 128, 256, GEMM_SMEM>>>(nullptr, sel_in, 3, NN, 0, 1,
                                                     gat_as + i * F, gat_ad + i * F,
                                                     nullptr, -1);
        k_agg<<<(NN + 7) / 8, 256>>>(gat_b + i * F, sel_out, (i < 2) ? (2 + i) : -1);
        int t = sel_in; sel_in = sel_out; sel_out = t;
    }
    // final conv output now in sel_in (g_h1)

    // ---- pooling ----
    k_pool<<<(NN + 63) / 64, 128>>>(batch, sel_in);

    // ---- lin layer: gbuf = relu(BN(pool) @ lin_w + lin_b) ----
    k_colstats<<<(NG + 63) / 64, 128>>>(nullptr, 4, NG, 4);
    k_fold<<<32, 128>>>(lin_w, bnfc_g, bnfc_b, 1.0f / (float)NG, 4);
    k_gemm<<<(NG + 127) / 128, 256, GEMM_SMEM>>>(nullptr, 4, 5, NG, 1, 0, nullptr, nullptr,
                                                 lin_b, 5);

    // ---- head: BN(gbuf) @ cls + log_softmax ----
    k_head<<<NG, 32>>>(bnh_g, bnh_b, cls_w, cls_b, out, 5);
}